// round 1
// baseline (speedup 1.0000x reference)
#include <cuda_runtime.h>
#include <math.h>

#define Nn 100000
#define Ee 1600000

// ---------------- scratch (__device__ globals; no runtime allocation) ----------------
__device__ __align__(16) float g_h[(size_t)Nn * 128];   // h1 = x@W1, then hrelu (in place)
__device__ __align__(16) float g_acc[(size_t)Nn * 128]; // acc1 (layer1 scatter), then hW2
__device__ __align__(16) float g_w[Ee];                 // sims, then edge weights (in place)
__device__ __align__(16) float g_rnrm[Nn];              // 1/max(||f||, eps)
__device__ __align__(16) float g_dr[Nn];                // deg_row -> dinv1 (in place)
__device__ __align__(16) float g_cnt[Nn];               // keep-count -> selfw=exp(1/(cnt+1))
__device__ __align__(16) float g_d2[Nn];                // gcn deg  -> dinv2 (in place)

__device__ __forceinline__ float warp_sum(float v) {
    #pragma unroll
    for (int o = 16; o; o >>= 1) v += __shfl_xor_sync(0xFFFFFFFFu, v, o);
    return v;
}
__device__ __forceinline__ float warp_max(float v) {
    #pragma unroll
    for (int o = 16; o; o >>= 1) v = fmaxf(v, __shfl_xor_sync(0xFFFFFFFFu, v, o));
    return v;
}

// ---------------- per-node reciprocal norm (warp per node) ----------------
__global__ void rnrm_kernel(const float* __restrict__ F) {
    int warp = (blockIdx.x * blockDim.x + threadIdx.x) >> 5;
    int lane = threadIdx.x & 31;
    if (warp >= Nn) return;
    float4 v = ((const float4*)F)[warp * 32 + lane];
    float s = v.x * v.x + v.y * v.y + v.z * v.z + v.w * v.w;
    s = warp_sum(s);
    if (lane == 0) g_rnrm[warp] = 1.0f / fmaxf(sqrtf(s), 1e-8f);
}

// ---------------- edge cosine sims + deg_row / keep-count (warp per edge) ----------------
__global__ void edge_dot(const float* __restrict__ F, const int* __restrict__ row,
                         const int* __restrict__ col) {
    int warp = (blockIdx.x * blockDim.x + threadIdx.x) >> 5;
    int lane = threadIdx.x & 31;
    if (warp >= Ee) return;
    int r = __ldg(row + warp);
    int c = __ldg(col + warp);
    float4 a = ((const float4*)F)[r * 32 + lane];
    float4 b = ((const float4*)F)[c * 32 + lane];
    float s = a.x * b.x + a.y * b.y + a.z * b.z + a.w * b.w;
    s = warp_sum(s);
    if (lane == 0) {
        float sim = s * g_rnrm[r] * g_rnrm[c];
        if (sim >= 0.1f) {
            g_w[warp] = sim;
            atomicAdd(g_dr + r, sim);
            atomicAdd(g_cnt + c, 1.0f);
        } else {
            g_w[warp] = 0.0f;
        }
    }
}

// ---------------- node: dinv1, selfw, init gcn-deg with self weight ----------------
__global__ void node1_kernel() {
    int n = blockIdx.x * blockDim.x + threadIdx.x;
    if (n >= Nn) return;
    float d = g_dr[n];
    g_dr[n] = (d > 0.0f) ? rsqrtf(d) : 0.0f;
    float sw = expf(1.0f / (g_cnt[n] + 1.0f));
    g_cnt[n] = sw;
    g_d2[n] = sw;   // gcn deg starts with the self-loop weight (col2 includes self)
}

// ---------------- edge weights + gcn degree over col ----------------
__global__ void edge_w_kernel(const int* __restrict__ row, const int* __restrict__ col) {
    int e = blockIdx.x * blockDim.x + threadIdx.x;
    if (e >= Ee) return;
    float s = g_w[e];
    if (s > 0.0f) {   // keep flag: kept edges have sims >= 0.1 > 0
        int r = __ldg(row + e), c = __ldg(col + e);
        float w = expf(g_dr[r] * s * g_dr[c]);   // normalized sim may be 0 -> exp(0)=1 (correct)
        g_w[e] = w;
        atomicAdd(g_d2 + c, w);
    }
}

__global__ void node2_kernel() {
    int n = blockIdx.x * blockDim.x + threadIdx.x;
    if (n >= Nn) return;
    float d = g_d2[n];
    g_d2[n] = (d > 0.0f) ? rsqrtf(d) : 0.0f;
}

// ---------------- scatter message passing (DO/4 lanes per edge) ----------------
template <int DO>
__global__ void edge_msg(const float* __restrict__ H, const int* __restrict__ row,
                         const int* __restrict__ col, float* __restrict__ out) {
    constexpr int L = DO / 4;   // lanes per edge (32 for DO=128, 16 for DO=64)
    int idx = blockIdx.x * blockDim.x + threadIdx.x;
    int e = idx / L;
    int lp = idx - e * L;
    if (e >= Ee) return;
    float w = g_w[e];
    if (w == 0.0f) return;
    int r = __ldg(row + e), c = __ldg(col + e);
    float coef = g_d2[r] * w * g_d2[c];
    float4 h = ((const float4*)(H + (size_t)r * DO))[lp];
    float* dst = out + (size_t)c * DO + lp * 4;
    asm volatile("red.global.add.v4.f32 [%0], {%1,%2,%3,%4};"
                 :: "l"(dst), "f"(h.x * coef), "f"(h.y * coef),
                    "f"(h.z * coef), "f"(h.w * coef) : "memory");
}

// ---------------- dense GEMM: out[N,C] = F[N,128] @ W[128,C] ----------------
template <int C>
__global__ void gemm_kernel(const float* __restrict__ F, const float* __restrict__ W,
                            float* __restrict__ out) {
    extern __shared__ float sm[];
    float* Ws = sm;              // 128*C
    float* Fs = sm + 128 * C;    // 64 rows * 132 (padded)
    int tid = threadIdx.x;

    float4* Ws4 = (float4*)Ws;
    const int wtot = 128 * C / 4;
    for (int i = tid; i < wtot; i += 256) Ws4[i] = ((const float4*)W)[i];

    int base = blockIdx.x * 64;
    for (int i = tid; i < 64 * 32; i += 256) {
        int nd = i >> 5, k4 = i & 31;
        float4 v = make_float4(0.f, 0.f, 0.f, 0.f);
        if (base + nd < Nn) v = ((const float4*)F)[(base + nd) * 32 + k4];
        *(float4*)(Fs + nd * 132 + k4 * 4) = v;
    }
    __syncthreads();

    constexpr int CG = C / 8;        // column groups of 8
    constexpr int NG = 256 / CG;     // node groups
    constexpr int NPT = 64 / NG;     // nodes per thread
    int cg = tid % CG;
    int ng = tid / CG;

    float acc[NPT][8];
    #pragma unroll
    for (int i = 0; i < NPT; i++)
        #pragma unroll
        for (int j = 0; j < 8; j++) acc[i][j] = 0.0f;

    #pragma unroll 4
    for (int k = 0; k < 128; k++) {
        float4 b0 = *(float4*)(Ws + k * C + cg * 8);
        float4 b1 = *(float4*)(Ws + k * C + cg * 8 + 4);
        #pragma unroll
        for (int i = 0; i < NPT; i++) {
            float a = Fs[(ng * NPT + i) * 132 + k];
            acc[i][0] += a * b0.x; acc[i][1] += a * b0.y;
            acc[i][2] += a * b0.z; acc[i][3] += a * b0.w;
            acc[i][4] += a * b1.x; acc[i][5] += a * b1.y;
            acc[i][6] += a * b1.z; acc[i][7] += a * b1.w;
        }
    }

    #pragma unroll
    for (int i = 0; i < NPT; i++) {
        int n = base + ng * NPT + i;
        if (n < Nn) {
            *(float4*)(out + (size_t)n * C + cg * 8) =
                make_float4(acc[i][0], acc[i][1], acc[i][2], acc[i][3]);
            *(float4*)(out + (size_t)n * C + cg * 8 + 4) =
                make_float4(acc[i][4], acc[i][5], acc[i][6], acc[i][7]);
        }
    }
}

// ---------------- LN(acc + self + b1) -> ReLU -> write into g_h (warp per node) ----------------
__global__ void ln_kernel(const float* __restrict__ b1, const float* __restrict__ lng,
                          const float* __restrict__ lnb) {
    int n = (blockIdx.x * blockDim.x + threadIdx.x) >> 5;
    int lane = threadIdx.x & 31;
    if (n >= Nn) return;
    float di = g_d2[n];
    float sc = di * di * g_cnt[n];             // dinv2^2 * selfw
    float4 a = ((const float4*)g_acc)[n * 32 + lane];
    float4 h = ((const float4*)g_h)[n * 32 + lane];
    float4 bv = ((const float4*)b1)[lane];
    float4 v;
    v.x = a.x + sc * h.x + bv.x;
    v.y = a.y + sc * h.y + bv.y;
    v.z = a.z + sc * h.z + bv.z;
    v.w = a.w + sc * h.w + bv.w;
    float s = warp_sum(v.x + v.y + v.z + v.w);
    float mu = s * (1.0f / 128.0f);
    float dx = v.x - mu, dy = v.y - mu, dz = v.z - mu, dw = v.w - mu;
    float q = warp_sum(dx * dx + dy * dy + dz * dz + dw * dw);
    float rs = rsqrtf(q * (1.0f / 128.0f) + 1e-5f);
    float4 gv = ((const float4*)lng)[lane];
    float4 ob = ((const float4*)lnb)[lane];
    float4 o;
    o.x = fmaxf(dx * rs * gv.x + ob.x, 0.0f);
    o.y = fmaxf(dy * rs * gv.y + ob.y, 0.0f);
    o.z = fmaxf(dz * rs * gv.z + ob.z, 0.0f);
    o.w = fmaxf(dw * rs * gv.w + ob.w, 0.0f);
    ((float4*)g_h)[n * 32 + lane] = o;
}

// ---------------- (acc2 + self + b2) -> log_softmax in place (warp per node) ----------------
__global__ void final_kernel(float* __restrict__ out, const float* __restrict__ b2) {
    int n = (blockIdx.x * blockDim.x + threadIdx.x) >> 5;
    int lane = threadIdx.x & 31;
    if (n >= Nn) return;
    float di = g_d2[n];
    float sc = di * di * g_cnt[n];
    const float* hw = g_acc + (size_t)n * 64;
    float* o = out + (size_t)n * 64;
    float v0 = o[lane]      + sc * hw[lane]      + b2[lane];
    float v1 = o[lane + 32] + sc * hw[lane + 32] + b2[lane + 32];
    float m = warp_max(fmaxf(v0, v1));
    float s = warp_sum(expf(v0 - m) + expf(v1 - m));
    float l = m + logf(s);
    o[lane]      = v0 - l;
    o[lane + 32] = v1 - l;
}

// ---------------- launch ----------------
extern "C" void kernel_launch(void* const* d_in, const int* in_sizes, int n_in,
                              void* d_out, int out_size) {
    const float* x   = (const float*)d_in[0];
    const int*   row = (const int*)d_in[1];
    const int*   col = (const int*)d_in[2];
    const float* W1  = (const float*)d_in[3];
    const float* b1  = (const float*)d_in[4];
    const float* lng = (const float*)d_in[5];
    const float* lnb = (const float*)d_in[6];
    const float* W2  = (const float*)d_in[7];
    const float* b2  = (const float*)d_in[8];
    float* out = (float*)d_out;

    void *p_h, *p_acc, *p_dr, *p_cnt;
    cudaGetSymbolAddress(&p_h, g_h);
    cudaGetSymbolAddress(&p_acc, g_acc);
    cudaGetSymbolAddress(&p_dr, g_dr);
    cudaGetSymbolAddress(&p_cnt, g_cnt);
    float* gh = (float*)p_h;
    float* gacc = (float*)p_acc;

    const size_t smem1 = (128 * 128 + 64 * 132) * sizeof(float);  // 99328
    const size_t smem2 = (128 * 64 + 64 * 132) * sizeof(float);   // 66560
    cudaFuncSetAttribute(gemm_kernel<128>, cudaFuncAttributeMaxDynamicSharedMemorySize, (int)smem1);
    cudaFuncSetAttribute(gemm_kernel<64>,  cudaFuncAttributeMaxDynamicSharedMemorySize, (int)smem2);

    const int NB_NODE_T = (Nn + 255) / 256;      // thread-per-node
    const int NB_NODE_W = (Nn * 32) / 256;       // warp-per-node (12500 exact)
    const int NB_EDGE_W = (Ee * 32) / 256;       // warp-per-edge (200000 exact)
    const int NB_EDGE_T = (Ee + 255) / 256;      // thread-per-edge
    const int NB_GEMM   = (Nn + 63) / 64;

    // ---- layer 1 ----
    cudaMemsetAsync(p_acc, 0, (size_t)Nn * 128 * sizeof(float));
    cudaMemsetAsync(p_dr,  0, (size_t)Nn * sizeof(float));
    cudaMemsetAsync(p_cnt, 0, (size_t)Nn * sizeof(float));
    cudaMemsetAsync(out,   0, (size_t)Nn * 64 * sizeof(float));

    rnrm_kernel<<<NB_NODE_W, 256>>>(x);
    gemm_kernel<128><<<NB_GEMM, 256, smem1>>>(x, W1, gh);
    edge_dot<<<NB_EDGE_W, 256>>>(x, row, col);
    node1_kernel<<<NB_NODE_T, 256>>>();
    edge_w_kernel<<<NB_EDGE_T, 256>>>(row, col);
    node2_kernel<<<NB_NODE_T, 256>>>();
    edge_msg<128><<<NB_EDGE_W, 256>>>(gh, row, col, gacc);
    ln_kernel<<<NB_NODE_W, 256>>>(b1, lng, lnb);

    // ---- layer 2 ----
    cudaMemsetAsync(p_dr,  0, (size_t)Nn * sizeof(float));
    cudaMemsetAsync(p_cnt, 0, (size_t)Nn * sizeof(float));

    rnrm_kernel<<<NB_NODE_W, 256>>>(gh);
    gemm_kernel<64><<<NB_GEMM, 256, smem2>>>(gh, W2, gacc);
    edge_dot<<<NB_EDGE_W, 256>>>(gh, row, col);
    node1_kernel<<<NB_NODE_T, 256>>>();
    edge_w_kernel<<<NB_EDGE_T, 256>>>(row, col);
    node2_kernel<<<NB_NODE_T, 256>>>();
    edge_msg<64><<<(Ee * 16) / 256, 256>>>(gacc, row, col, out);
    final_kernel<<<NB_NODE_W, 256>>>(out, b2);
}

// round 2
// speedup vs baseline: 1.4766x; 1.4766x over previous
#include <cuda_runtime.h>
#include <math.h>

#define Nn 100000
#define Ee 1600000
#define NSCAN (Nn + 1)
#define SCAN_B 98   // ceil(100001/1024)

// ---------------- scratch (__device__ globals; no runtime allocation) ----------------
__device__ __align__(16) float g_h[(size_t)Nn * 128];   // h1 = x@W1 ; later hW2 (layer2)
__device__ __align__(16) float g_acc[(size_t)Nn * 128]; // relu(LN(...)) output of layer 1
__device__ __align__(16) float g_w[Ee];                 // sims, then edge weights (CSC order)
__device__ int g_srow[Ee];                              // row index per CSC-sorted edge
__device__ int g_hist[SCAN_B * 1024];
__device__ int g_ptr[SCAN_B * 1024];                    // CSC col pointers (exclusive scan)
__device__ int g_pos[Nn];
__device__ int g_bsum[SCAN_B], g_boff[SCAN_B];
__device__ float g_rnrm[Nn];                            // 1/max(||f||, eps)
__device__ float g_dr[Nn];                              // deg_row -> dinv1 (in place)
__device__ float g_cnt[Nn];                             // selfw = exp(1/(kept_in+1))
__device__ float g_d2[Nn];                              // dinv2 = rsqrt(gcn degree)

__device__ __forceinline__ float warp_sum(float v) {
    #pragma unroll
    for (int o = 16; o; o >>= 1) v += __shfl_xor_sync(0xFFFFFFFFu, v, o);
    return v;
}
__device__ __forceinline__ float warp_max(float v) {
    #pragma unroll
    for (int o = 16; o; o >>= 1) v = fmaxf(v, __shfl_xor_sync(0xFFFFFFFFu, v, o));
    return v;
}

// ======================= CSC build (once; row/col are fixed inputs) ==================
__global__ void hist_kernel(const int* __restrict__ col) {
    int e = blockIdx.x * blockDim.x + threadIdx.x;
    if (e < Ee) atomicAdd(&g_hist[__ldg(col + e)], 1);
}

__global__ void scan1_kernel() {
    __shared__ int s[1024];
    int tid = threadIdx.x;
    int i = blockIdx.x * 1024 + tid;
    int v = (i < NSCAN) ? g_hist[i] : 0;
    s[tid] = v;
    __syncthreads();
    #pragma unroll
    for (int off = 1; off < 1024; off <<= 1) {
        int t = (tid >= off) ? s[tid - off] : 0;
        __syncthreads();
        s[tid] += t;
        __syncthreads();
    }
    g_ptr[i] = s[tid] - v;                     // exclusive within block
    if (tid == 1023) g_bsum[blockIdx.x] = s[1023];
}

__global__ void scan2_kernel() {
    __shared__ int s[128];
    int tid = threadIdx.x;
    int v = (tid < SCAN_B) ? g_bsum[tid] : 0;
    s[tid] = v;
    __syncthreads();
    #pragma unroll
    for (int off = 1; off < 128; off <<= 1) {
        int t = (tid >= off) ? s[tid - off] : 0;
        __syncthreads();
        s[tid] += t;
        __syncthreads();
    }
    if (tid < SCAN_B) g_boff[tid] = s[tid] - v;
}

__global__ void scan3_kernel() {
    int i = blockIdx.x * 1024 + threadIdx.x;
    int val = g_ptr[i] + g_boff[blockIdx.x];
    g_ptr[i] = val;
    if (i < Nn) g_pos[i] = val;
}

__global__ void scatter_kernel(const int* __restrict__ row, const int* __restrict__ col) {
    int e = blockIdx.x * blockDim.x + threadIdx.x;
    if (e >= Ee) return;
    int c = __ldg(col + e);
    int p = atomicAdd(&g_pos[c], 1);
    g_srow[p] = __ldg(row + e);
}

// ======================= per-layer stages ==============================

// per-node reciprocal norm (warp per node)
__global__ void rnrm_kernel(const float* __restrict__ F) {
    int n = (blockIdx.x * blockDim.x + threadIdx.x) >> 5;
    int lane = threadIdx.x & 31;
    if (n >= Nn) return;
    float4 v = ((const float4*)F)[(size_t)n * 32 + lane];
    float s = warp_sum(v.x * v.x + v.y * v.y + v.z * v.z + v.w * v.w);
    if (lane == 0) g_rnrm[n] = 1.0f / fmaxf(sqrtf(s), 1e-8f);
}

// cosine sims, node-centric: warp per col-node; F[col] held in registers.
__global__ void edge_dot(const float* __restrict__ F) {
    int n = (blockIdx.x * blockDim.x + threadIdx.x) >> 5;
    int lane = threadIdx.x & 31;
    if (n >= Nn) return;
    float4 f = ((const float4*)F)[(size_t)n * 32 + lane];
    float rc = g_rnrm[n];
    int beg = g_ptr[n], end = g_ptr[n + 1];
    for (int i = beg; i < end; i++) {
        int r = __ldg(g_srow + i);
        float4 a = ((const float4*)F)[(size_t)r * 32 + lane];
        float s = warp_sum(a.x * f.x + a.y * f.y + a.z * f.z + a.w * f.w);
        if (lane == 0) {
            float sim = s * g_rnrm[r] * rc;
            if (sim >= 0.1f) {
                g_w[i] = sim;
                atomicAdd(g_dr + r, sim);
            } else {
                g_w[i] = 0.0f;
            }
        }
    }
}

// deg_row -> dinv1
__global__ void dinv_kernel() {
    int n = blockIdx.x * blockDim.x + threadIdx.x;
    if (n >= Nn) return;
    float d = g_dr[n];
    g_dr[n] = (d > 0.0f) ? rsqrtf(d) : 0.0f;
}

// per col-node: edge weights w=exp(dinv1[r]*sim*dinv1[c]), kept-count -> selfw,
// gcn degree -> dinv2. No atomics (segment-local).
__global__ void edge_w_kernel() {
    int n = (blockIdx.x * blockDim.x + threadIdx.x) >> 5;
    int lane = threadIdx.x & 31;
    if (n >= Nn) return;
    int beg = g_ptr[n], end = g_ptr[n + 1];
    float dc = g_dr[n];
    float deg2 = 0.0f;
    int cnt = 0;
    for (int i = beg + lane; i < end; i += 32) {
        float s = g_w[i];
        if (s > 0.0f) {
            cnt++;
            float w = expf(g_dr[__ldg(g_srow + i)] * s * dc);
            g_w[i] = w;
            deg2 += w;
        }
    }
    deg2 = warp_sum(deg2);
    cnt = __reduce_add_sync(0xFFFFFFFFu, cnt);
    if (lane == 0) {
        float selfw = expf(1.0f / (float)(cnt + 1));
        g_cnt[n] = selfw;
        g_d2[n] = rsqrtf(deg2 + selfw);   // always > 0 (selfw >= 1)
    }
}

// ======================= dense GEMM with packed fma.rn.f32x2 =========================
#define PK2(d, x)  asm("mov.b64 %0, {%1, %1};" : "=l"(d) : "r"(__float_as_uint(x)))
#define FMA2(d, a, b) asm("fma.rn.f32x2 %0, %1, %2, %0;" : "+l"(d) : "l"(a), "l"(b))
#define UPK2(lo, hi, d) asm("mov.b64 {%0, %1}, %2;" : "=r"(lo), "=r"(hi) : "l"(d))

template <int C>
__global__ void gemm_kernel(const float* __restrict__ F, const float* __restrict__ W,
                            float* __restrict__ out) {
    constexpr int CG = C / 8;          // col groups of 8
    constexpr int NG = 256 / CG;
    constexpr int NPT = 4;
    constexpr int TILE = NG * NPT;     // C=128 -> 64 nodes, C=64 -> 128 nodes
    extern __shared__ float sm[];
    float* Ws = sm;                    // 128*C
    float* Fs = sm + 128 * C;          // TILE*132 (padded)
    int tid = threadIdx.x;

    for (int i = tid; i < 128 * C / 4; i += 256)
        ((float4*)Ws)[i] = ((const float4*)W)[i];

    int base = blockIdx.x * TILE;
    for (int i = tid; i < TILE * 32; i += 256) {
        int nd = i >> 5, k4 = i & 31;
        float4 v = make_float4(0.f, 0.f, 0.f, 0.f);
        if (base + nd < Nn) v = ((const float4*)F)[(size_t)(base + nd) * 32 + k4];
        *(float4*)(Fs + nd * 132 + k4 * 4) = v;
    }
    __syncthreads();

    int cg = tid % CG, ng = tid / CG;
    unsigned long long acc[NPT][4];
    #pragma unroll
    for (int i = 0; i < NPT; i++)
        #pragma unroll
        for (int j = 0; j < 4; j++) acc[i][j] = 0ull;

    #pragma unroll 4
    for (int k = 0; k < 128; k++) {
        const unsigned long long* bp = (const unsigned long long*)(Ws + k * C + cg * 8);
        unsigned long long B0 = bp[0], B1 = bp[1], B2 = bp[2], B3 = bp[3];
        #pragma unroll
        for (int i = 0; i < NPT; i++) {
            float a = Fs[(ng * NPT + i) * 132 + k];
            unsigned long long ap; PK2(ap, a);
            FMA2(acc[i][0], ap, B0);
            FMA2(acc[i][1], ap, B1);
            FMA2(acc[i][2], ap, B2);
            FMA2(acc[i][3], ap, B3);
        }
    }

    #pragma unroll
    for (int i = 0; i < NPT; i++) {
        int n = base + ng * NPT + i;
        if (n < Nn) {
            unsigned int o[8];
            #pragma unroll
            for (int j = 0; j < 4; j++) UPK2(o[2 * j], o[2 * j + 1], acc[i][j]);
            *(uint4*)(out + (size_t)n * C + cg * 8) = make_uint4(o[0], o[1], o[2], o[3]);
            *(uint4*)(out + (size_t)n * C + cg * 8 + 4) = make_uint4(o[4], o[5], o[6], o[7]);
        }
    }
}

// ========== fused layer-1 aggregate: gather + self + b1 + LayerNorm + ReLU ==========
// Also computes rnrm of the output (needed by layer-2 edge_dot). warp per node.
__global__ void fused1_kernel(const float* __restrict__ H, const float* __restrict__ b1,
                              const float* __restrict__ lng, const float* __restrict__ lnb,
                              float* __restrict__ O) {
    int n = (blockIdx.x * blockDim.x + threadIdx.x) >> 5;
    int lane = threadIdx.x & 31;
    if (n >= Nn) return;
    int beg = g_ptr[n], end = g_ptr[n + 1];
    float d2n = g_d2[n];
    float sc = g_cnt[n] * d2n;                 // x d2n again at the end -> dinv2^2*selfw
    float4 hv = ((const float4*)H)[(size_t)n * 32 + lane];
    float4 acc = make_float4(sc * hv.x, sc * hv.y, sc * hv.z, sc * hv.w);
    for (int i = beg; i < end; i++) {
        float w = g_w[i];
        if (w != 0.0f) {
            int r = __ldg(g_srow + i);
            float cf = w * g_d2[r];
            float4 h = ((const float4*)H)[(size_t)r * 32 + lane];
            acc.x += cf * h.x; acc.y += cf * h.y;
            acc.z += cf * h.z; acc.w += cf * h.w;
        }
    }
    float4 bv = ((const float4*)b1)[lane];
    float vx = acc.x * d2n + bv.x, vy = acc.y * d2n + bv.y;
    float vz = acc.z * d2n + bv.z, vw = acc.w * d2n + bv.w;
    float mu = warp_sum(vx + vy + vz + vw) * (1.0f / 128.0f);
    float dx = vx - mu, dy = vy - mu, dz = vz - mu, dw = vw - mu;
    float q = warp_sum(dx * dx + dy * dy + dz * dz + dw * dw);
    float rs = rsqrtf(q * (1.0f / 128.0f) + 1e-5f);
    float4 gv = ((const float4*)lng)[lane];
    float4 ob = ((const float4*)lnb)[lane];
    float4 o;
    o.x = fmaxf(dx * rs * gv.x + ob.x, 0.0f);
    o.y = fmaxf(dy * rs * gv.y + ob.y, 0.0f);
    o.z = fmaxf(dz * rs * gv.z + ob.z, 0.0f);
    o.w = fmaxf(dw * rs * gv.w + ob.w, 0.0f);
    ((float4*)O)[(size_t)n * 32 + lane] = o;
    // rnrm of layer-1 output for layer-2 attention
    float ss = warp_sum(o.x * o.x + o.y * o.y + o.z * o.z + o.w * o.w);
    if (lane == 0) g_rnrm[n] = 1.0f / fmaxf(sqrtf(ss), 1e-8f);
}

// ========== fused layer-2 aggregate: gather + self + b2 + log_softmax ==========
__global__ void fused2_kernel(const float* __restrict__ H, const float* __restrict__ b2,
                              float* __restrict__ out) {
    int n = (blockIdx.x * blockDim.x + threadIdx.x) >> 5;
    int lane = threadIdx.x & 31;
    if (n >= Nn) return;
    int beg = g_ptr[n], end = g_ptr[n + 1];
    float d2n = g_d2[n];
    float sc = g_cnt[n] * d2n;
    float2 hv = ((const float2*)H)[(size_t)n * 32 + lane];
    float2 acc = make_float2(sc * hv.x, sc * hv.y);
    for (int i = beg; i < end; i++) {
        float w = g_w[i];
        if (w != 0.0f) {
            int r = __ldg(g_srow + i);
            float cf = w * g_d2[r];
            float2 h = ((const float2*)H)[(size_t)r * 32 + lane];
            acc.x += cf * h.x; acc.y += cf * h.y;
        }
    }
    float2 bv = ((const float2*)b2)[lane];
    float v0 = acc.x * d2n + bv.x;
    float v1 = acc.y * d2n + bv.y;
    float m = warp_max(fmaxf(v0, v1));
    float s = warp_sum(expf(v0 - m) + expf(v1 - m));
    float l = m + logf(s);
    ((float2*)out)[(size_t)n * 32 + lane] = make_float2(v0 - l, v1 - l);
}

// ======================= launch ==============================
extern "C" void kernel_launch(void* const* d_in, const int* in_sizes, int n_in,
                              void* d_out, int out_size) {
    const float* x   = (const float*)d_in[0];
    const int*   row = (const int*)d_in[1];
    const int*   col = (const int*)d_in[2];
    const float* W1  = (const float*)d_in[3];
    const float* b1  = (const float*)d_in[4];
    const float* lng = (const float*)d_in[5];
    const float* lnb = (const float*)d_in[6];
    const float* W2  = (const float*)d_in[7];
    const float* b2  = (const float*)d_in[8];
    float* out = (float*)d_out;

    void *p_h, *p_acc, *p_dr, *p_hist;
    cudaGetSymbolAddress(&p_h, g_h);
    cudaGetSymbolAddress(&p_acc, g_acc);
    cudaGetSymbolAddress(&p_dr, g_dr);
    cudaGetSymbolAddress(&p_hist, g_hist);
    float* gh = (float*)p_h;
    float* gacc = (float*)p_acc;

    const size_t smem1 = (128 * 128 + 64 * 132) * sizeof(float);   // 99328
    const size_t smem2 = (128 * 64 + 128 * 132) * sizeof(float);   // 100352
    cudaFuncSetAttribute(gemm_kernel<128>, cudaFuncAttributeMaxDynamicSharedMemorySize, (int)smem1);
    cudaFuncSetAttribute(gemm_kernel<64>,  cudaFuncAttributeMaxDynamicSharedMemorySize, (int)smem2);

    const int NB_NODE_T = (Nn + 255) / 256;
    const int NB_NODE_W = (Nn * 32) / 256;     // warp-per-node, 12500 exact
    const int NB_EDGE_T = (Ee + 255) / 256;

    // ---- CSC build (row/col fixed; rebuilt each call deterministically up to fp order) ----
    cudaMemsetAsync(p_hist, 0, NSCAN * sizeof(int));
    hist_kernel<<<NB_EDGE_T, 256>>>(col);
    scan1_kernel<<<SCAN_B, 1024>>>();
    scan2_kernel<<<1, 128>>>();
    scan3_kernel<<<SCAN_B, 1024>>>();
    scatter_kernel<<<NB_EDGE_T, 256>>>(row, col);

    // ---- layer 1 ----
    cudaMemsetAsync(p_dr, 0, Nn * sizeof(float));
    rnrm_kernel<<<NB_NODE_W, 256>>>(x);
    gemm_kernel<128><<<(Nn + 63) / 64, 256, smem1>>>(x, W1, gh);
    edge_dot<<<NB_NODE_W, 256>>>(x);
    dinv_kernel<<<NB_NODE_T, 256>>>();
    edge_w_kernel<<<NB_NODE_W, 256>>>();
    fused1_kernel<<<NB_NODE_W, 256>>>(gh, b1, lng, lnb, gacc);

    // ---- layer 2 ----
    cudaMemsetAsync(p_dr, 0, Nn * sizeof(float));
    gemm_kernel<64><<<(Nn + 127) / 128, 256, smem2>>>(gacc, W2, gh);
    edge_dot<<<NB_NODE_W, 256>>>(gacc);
    dinv_kernel<<<NB_NODE_T, 256>>>();
    edge_w_kernel<<<NB_NODE_W, 256>>>();
    fused2_kernel<<<NB_NODE_W, 256>>>(gh, b2, out);
}

// round 3
// speedup vs baseline: 1.5311x; 1.0369x over previous
#include <cuda_runtime.h>
#include <math.h>

#define Nn 100000
#define Ee 1600000
#define NSCAN (Nn + 1)
#define SCAN_B 98   // ceil(100001/1024)

// ---------------- scratch (__device__ globals; no runtime allocation) ----------------
__device__ __align__(16) float g_h[(size_t)Nn * 128];   // h1 = x@W1 ; later hW2 (layer2)
__device__ __align__(16) float g_acc[(size_t)Nn * 128]; // relu(LN(...)) output of layer 1
__device__ __align__(16) float g_w[Ee];                 // sims, then edge weights (CSC order)
__device__ int g_srow[Ee];                              // row index per CSC-sorted edge
__device__ int g_hist[SCAN_B * 1024];
__device__ int g_ptr[SCAN_B * 1024];                    // CSC col pointers (exclusive scan)
__device__ int g_pos[Nn];
__device__ int g_bsum[SCAN_B], g_boff[SCAN_B];
__device__ float g_rnrm[Nn];                            // 1/max(||f||, eps)
__device__ float g_dr[Nn];                              // deg_row -> dinv1 (in place)
__device__ float g_cnt[Nn];                             // selfw = exp(1/(kept_in+1))
__device__ float g_d2[Nn];                              // dinv2 = rsqrt(gcn degree)

__device__ __forceinline__ float warp_sum(float v) {
    #pragma unroll
    for (int o = 16; o; o >>= 1) v += __shfl_xor_sync(0xFFFFFFFFu, v, o);
    return v;
}
__device__ __forceinline__ float warp_max(float v) {
    #pragma unroll
    for (int o = 16; o; o >>= 1) v = fmaxf(v, __shfl_xor_sync(0xFFFFFFFFu, v, o));
    return v;
}

// ======================= CSC build (once; row/col are fixed inputs) ==================
__global__ void hist_kernel(const int* __restrict__ col) {
    int e = blockIdx.x * blockDim.x + threadIdx.x;
    if (e < Ee) atomicAdd(&g_hist[__ldg(col + e)], 1);
}

__global__ void scan1_kernel() {
    __shared__ int s[1024];
    int tid = threadIdx.x;
    int i = blockIdx.x * 1024 + tid;
    int v = (i < NSCAN) ? g_hist[i] : 0;
    s[tid] = v;
    __syncthreads();
    #pragma unroll
    for (int off = 1; off < 1024; off <<= 1) {
        int t = (tid >= off) ? s[tid - off] : 0;
        __syncthreads();
        s[tid] += t;
        __syncthreads();
    }
    g_ptr[i] = s[tid] - v;                     // exclusive within block
    if (tid == 1023) g_bsum[blockIdx.x] = s[1023];
}

__global__ void scan2_kernel() {
    __shared__ int s[128];
    int tid = threadIdx.x;
    int v = (tid < SCAN_B) ? g_bsum[tid] : 0;
    s[tid] = v;
    __syncthreads();
    #pragma unroll
    for (int off = 1; off < 128; off <<= 1) {
        int t = (tid >= off) ? s[tid - off] : 0;
        __syncthreads();
        s[tid] += t;
        __syncthreads();
    }
    if (tid < SCAN_B) g_boff[tid] = s[tid] - v;
}

__global__ void scan3_kernel() {
    int i = blockIdx.x * 1024 + threadIdx.x;
    int val = g_ptr[i] + g_boff[blockIdx.x];
    g_ptr[i] = val;
    if (i < Nn) g_pos[i] = val;
}

__global__ void scatter_kernel(const int* __restrict__ row, const int* __restrict__ col) {
    int e = blockIdx.x * blockDim.x + threadIdx.x;
    if (e >= Ee) return;
    int c = __ldg(col + e);
    int p = atomicAdd(&g_pos[c], 1);
    g_srow[p] = __ldg(row + e);
}

// ======================= per-layer stages ==============================

// per-node reciprocal norm (warp per node)
__global__ void rnrm_kernel(const float* __restrict__ F) {
    int n = (blockIdx.x * blockDim.x + threadIdx.x) >> 5;
    int lane = threadIdx.x & 31;
    if (n >= Nn) return;
    float4 v = ((const float4*)F)[(size_t)n * 32 + lane];
    float s = warp_sum(v.x * v.x + v.y * v.y + v.z * v.z + v.w * v.w);
    if (lane == 0) g_rnrm[n] = 1.0f / fmaxf(sqrtf(s), 1e-8f);
}

// cosine sims, node-centric, 4 edges in flight per warp.
__global__ void edge_dot(const float* __restrict__ F) {
    int n = (blockIdx.x * blockDim.x + threadIdx.x) >> 5;
    int lane = threadIdx.x & 31;
    if (n >= Nn) return;
    float4 f = ((const float4*)F)[(size_t)n * 32 + lane];
    float rc = g_rnrm[n];
    int beg = g_ptr[n], end = g_ptr[n + 1];
    for (int i = beg; i < end; i += 4) {
        int m = end - i;                              // >= 1
        int i1 = i + (m > 1 ? 1 : 0);
        int i2 = i + (m > 2 ? 2 : 0);
        int i3 = i + (m > 3 ? 3 : 0);
        int r0 = __ldg(g_srow + i);
        int r1 = __ldg(g_srow + i1);
        int r2 = __ldg(g_srow + i2);
        int r3 = __ldg(g_srow + i3);
        float4 a0 = ((const float4*)F)[(size_t)r0 * 32 + lane];
        float4 a1 = ((const float4*)F)[(size_t)r1 * 32 + lane];
        float4 a2 = ((const float4*)F)[(size_t)r2 * 32 + lane];
        float4 a3 = ((const float4*)F)[(size_t)r3 * 32 + lane];
        float s0 = a0.x * f.x + a0.y * f.y + a0.z * f.z + a0.w * f.w;
        float s1 = a1.x * f.x + a1.y * f.y + a1.z * f.z + a1.w * f.w;
        float s2 = a2.x * f.x + a2.y * f.y + a2.z * f.z + a2.w * f.w;
        float s3 = a3.x * f.x + a3.y * f.y + a3.z * f.z + a3.w * f.w;
        #pragma unroll
        for (int o = 16; o; o >>= 1) {               // 4 interleaved butterflies
            s0 += __shfl_xor_sync(0xFFFFFFFFu, s0, o);
            s1 += __shfl_xor_sync(0xFFFFFFFFu, s1, o);
            s2 += __shfl_xor_sync(0xFFFFFFFFu, s2, o);
            s3 += __shfl_xor_sync(0xFFFFFFFFu, s3, o);
        }
        if (lane < 4 && lane < m) {                   // lane k finalizes edge i+k
            float s = (lane == 0) ? s0 : (lane == 1) ? s1 : (lane == 2) ? s2 : s3;
            int   r = (lane == 0) ? r0 : (lane == 1) ? r1 : (lane == 2) ? r2 : r3;
            float sim = s * g_rnrm[r] * rc;
            if (sim >= 0.1f) {
                g_w[i + lane] = sim;
                atomicAdd(g_dr + r, sim);
            } else {
                g_w[i + lane] = 0.0f;
            }
        }
    }
}

// deg_row -> dinv1
__global__ void dinv_kernel() {
    int n = blockIdx.x * blockDim.x + threadIdx.x;
    if (n >= Nn) return;
    float d = g_dr[n];
    g_dr[n] = (d > 0.0f) ? rsqrtf(d) : 0.0f;
}

// per col-node: edge weights w=exp(dinv1[r]*sim*dinv1[c]), kept-count -> selfw,
// gcn degree -> dinv2. No atomics (segment-local).
__global__ void edge_w_kernel() {
    int n = (blockIdx.x * blockDim.x + threadIdx.x) >> 5;
    int lane = threadIdx.x & 31;
    if (n >= Nn) return;
    int beg = g_ptr[n], end = g_ptr[n + 1];
    float dc = g_dr[n];
    float deg2 = 0.0f;
    int cnt = 0;
    for (int i = beg + lane; i < end; i += 32) {
        float s = g_w[i];
        if (s > 0.0f) {
            cnt++;
            float w = expf(g_dr[__ldg(g_srow + i)] * s * dc);
            g_w[i] = w;
            deg2 += w;
        }
    }
    deg2 = warp_sum(deg2);
    cnt = __reduce_add_sync(0xFFFFFFFFu, cnt);
    if (lane == 0) {
        float selfw = expf(1.0f / (float)(cnt + 1));
        g_cnt[n] = selfw;
        g_d2[n] = rsqrtf(deg2 + selfw);   // always > 0 (selfw >= 1)
    }
}

// ======================= dense GEMM with packed fma.rn.f32x2 =========================
#define PK2(d, x)  asm("mov.b64 %0, {%1, %1};" : "=l"(d) : "r"(__float_as_uint(x)))
#define FMA2(d, a, b) asm("fma.rn.f32x2 %0, %1, %2, %0;" : "+l"(d) : "l"(a), "l"(b))
#define UPK2(lo, hi, d) asm("mov.b64 {%0, %1}, %2;" : "=r"(lo), "=r"(hi) : "l"(d))

template <int C>
__global__ void gemm_kernel(const float* __restrict__ F, const float* __restrict__ W,
                            float* __restrict__ out) {
    constexpr int CG = C / 8;          // col groups of 8
    constexpr int NG = 256 / CG;
    constexpr int NPT = 4;
    constexpr int TILE = NG * NPT;     // C=128 -> 64 nodes, C=64 -> 128 nodes
    extern __shared__ float sm[];
    float* Ws = sm;                    // 128*C
    float* Fs = sm + 128 * C;          // TILE*132 (padded)
    int tid = threadIdx.x;

    for (int i = tid; i < 128 * C / 4; i += 256)
        ((float4*)Ws)[i] = ((const float4*)W)[i];

    int base = blockIdx.x * TILE;
    for (int i = tid; i < TILE * 32; i += 256) {
        int nd = i >> 5, k4 = i & 31;
        float4 v = make_float4(0.f, 0.f, 0.f, 0.f);
        if (base + nd < Nn) v = ((const float4*)F)[(size_t)(base + nd) * 32 + k4];
        *(float4*)(Fs + nd * 132 + k4 * 4) = v;
    }
    __syncthreads();

    int cg = tid % CG, ng = tid / CG;
    unsigned long long acc[NPT][4];
    #pragma unroll
    for (int i = 0; i < NPT; i++)
        #pragma unroll
        for (int j = 0; j < 4; j++) acc[i][j] = 0ull;

    #pragma unroll 4
    for (int k = 0; k < 128; k++) {
        const unsigned long long* bp = (const unsigned long long*)(Ws + k * C + cg * 8);
        unsigned long long B0 = bp[0], B1 = bp[1], B2 = bp[2], B3 = bp[3];
        #pragma unroll
        for (int i = 0; i < NPT; i++) {
            float a = Fs[(ng * NPT + i) * 132 + k];
            unsigned long long ap; PK2(ap, a);
            FMA2(acc[i][0], ap, B0);
            FMA2(acc[i][1], ap, B1);
            FMA2(acc[i][2], ap, B2);
            FMA2(acc[i][3], ap, B3);
        }
    }

    #pragma unroll
    for (int i = 0; i < NPT; i++) {
        int n = base + ng * NPT + i;
        if (n < Nn) {
            unsigned int o[8];
            #pragma unroll
            for (int j = 0; j < 4; j++) UPK2(o[2 * j], o[2 * j + 1], acc[i][j]);
            *(uint4*)(out + (size_t)n * C + cg * 8) = make_uint4(o[0], o[1], o[2], o[3]);
            *(uint4*)(out + (size_t)n * C + cg * 8 + 4) = make_uint4(o[4], o[5], o[6], o[7]);
        }
    }
}

// ========== fused layer-1 aggregate: gather + self + b1 + LayerNorm + ReLU ==========
// Also computes rnrm of the output (needed by layer-2 edge_dot). warp per node.
__global__ void fused1_kernel(const float* __restrict__ H, const float* __restrict__ b1,
                              const float* __restrict__ lng, const float* __restrict__ lnb,
                              float* __restrict__ O) {
    int n = (blockIdx.x * blockDim.x + threadIdx.x) >> 5;
    int lane = threadIdx.x & 31;
    if (n >= Nn) return;
    int beg = g_ptr[n], end = g_ptr[n + 1];
    float d2n = g_d2[n];
    float sc = g_cnt[n] * d2n;                 // x d2n again at the end -> dinv2^2*selfw
    float4 hv = ((const float4*)H)[(size_t)n * 32 + lane];
    float4 acc = make_float4(sc * hv.x, sc * hv.y, sc * hv.z, sc * hv.w);
    for (int i = beg; i < end; i += 4) {
        int m = end - i;
        int i1 = i + (m > 1 ? 1 : 0);
        int i2 = i + (m > 2 ? 2 : 0);
        int i3 = i + (m > 3 ? 3 : 0);
        float w0 = g_w[i];
        float w1 = (m > 1) ? g_w[i1] : 0.0f;
        float w2 = (m > 2) ? g_w[i2] : 0.0f;
        float w3 = (m > 3) ? g_w[i3] : 0.0f;
        int r0 = __ldg(g_srow + i);
        int r1 = __ldg(g_srow + i1);
        int r2 = __ldg(g_srow + i2);
        int r3 = __ldg(g_srow + i3);
        if (w0 != 0.0f) {
            float cf = w0 * g_d2[r0];
            float4 h = ((const float4*)H)[(size_t)r0 * 32 + lane];
            acc.x += cf * h.x; acc.y += cf * h.y; acc.z += cf * h.z; acc.w += cf * h.w;
        }
        if (w1 != 0.0f) {
            float cf = w1 * g_d2[r1];
            float4 h = ((const float4*)H)[(size_t)r1 * 32 + lane];
            acc.x += cf * h.x; acc.y += cf * h.y; acc.z += cf * h.z; acc.w += cf * h.w;
        }
        if (w2 != 0.0f) {
            float cf = w2 * g_d2[r2];
            float4 h = ((const float4*)H)[(size_t)r2 * 32 + lane];
            acc.x += cf * h.x; acc.y += cf * h.y; acc.z += cf * h.z; acc.w += cf * h.w;
        }
        if (w3 != 0.0f) {
            float cf = w3 * g_d2[r3];
            float4 h = ((const float4*)H)[(size_t)r3 * 32 + lane];
            acc.x += cf * h.x; acc.y += cf * h.y; acc.z += cf * h.z; acc.w += cf * h.w;
        }
    }
    float4 bv = ((const float4*)b1)[lane];
    float vx = acc.x * d2n + bv.x, vy = acc.y * d2n + bv.y;
    float vz = acc.z * d2n + bv.z, vw = acc.w * d2n + bv.w;
    float mu = warp_sum(vx + vy + vz + vw) * (1.0f / 128.0f);
    float dx = vx - mu, dy = vy - mu, dz = vz - mu, dw = vw - mu;
    float q = warp_sum(dx * dx + dy * dy + dz * dz + dw * dw);
    float rs = rsqrtf(q * (1.0f / 128.0f) + 1e-5f);
    float4 gv = ((const float4*)lng)[lane];
    float4 ob = ((const float4*)lnb)[lane];
    float4 o;
    o.x = fmaxf(dx * rs * gv.x + ob.x, 0.0f);
    o.y = fmaxf(dy * rs * gv.y + ob.y, 0.0f);
    o.z = fmaxf(dz * rs * gv.z + ob.z, 0.0f);
    o.w = fmaxf(dw * rs * gv.w + ob.w, 0.0f);
    ((float4*)O)[(size_t)n * 32 + lane] = o;
    // rnrm of layer-1 output for layer-2 attention
    float ss = warp_sum(o.x * o.x + o.y * o.y + o.z * o.z + o.w * o.w);
    if (lane == 0) g_rnrm[n] = 1.0f / fmaxf(sqrtf(ss), 1e-8f);
}

// ========== fused layer-2 aggregate: gather + self + b2 + log_softmax ==========
__global__ void fused2_kernel(const float* __restrict__ H, const float* __restrict__ b2,
                              float* __restrict__ out) {
    int n = (blockIdx.x * blockDim.x + threadIdx.x) >> 5;
    int lane = threadIdx.x & 31;
    if (n >= Nn) return;
    int beg = g_ptr[n], end = g_ptr[n + 1];
    float d2n = g_d2[n];
    float sc = g_cnt[n] * d2n;
    float2 hv = ((const float2*)H)[(size_t)n * 32 + lane];
    float2 acc = make_float2(sc * hv.x, sc * hv.y);
    for (int i = beg; i < end; i += 4) {
        int m = end - i;
        int i1 = i + (m > 1 ? 1 : 0);
        int i2 = i + (m > 2 ? 2 : 0);
        int i3 = i + (m > 3 ? 3 : 0);
        float w0 = g_w[i];
        float w1 = (m > 1) ? g_w[i1] : 0.0f;
        float w2 = (m > 2) ? g_w[i2] : 0.0f;
        float w3 = (m > 3) ? g_w[i3] : 0.0f;
        int r0 = __ldg(g_srow + i);
        int r1 = __ldg(g_srow + i1);
        int r2 = __ldg(g_srow + i2);
        int r3 = __ldg(g_srow + i3);
        if (w0 != 0.0f) {
            float cf = w0 * g_d2[r0];
            float2 h = ((const float2*)H)[(size_t)r0 * 32 + lane];
            acc.x += cf * h.x; acc.y += cf * h.y;
        }
        if (w1 != 0.0f) {
            float cf = w1 * g_d2[r1];
            float2 h = ((const float2*)H)[(size_t)r1 * 32 + lane];
            acc.x += cf * h.x; acc.y += cf * h.y;
        }
        if (w2 != 0.0f) {
            float cf = w2 * g_d2[r2];
            float2 h = ((const float2*)H)[(size_t)r2 * 32 + lane];
            acc.x += cf * h.x; acc.y += cf * h.y;
        }
        if (w3 != 0.0f) {
            float cf = w3 * g_d2[r3];
            float2 h = ((const float2*)H)[(size_t)r3 * 32 + lane];
            acc.x += cf * h.x; acc.y += cf * h.y;
        }
    }
    float2 bv = ((const float2*)b2)[lane];
    float v0 = acc.x * d2n + bv.x;
    float v1 = acc.y * d2n + bv.y;
    float m = warp_max(fmaxf(v0, v1));
    float s = warp_sum(expf(v0 - m) + expf(v1 - m));
    float l = m + logf(s);
    ((float2*)out)[(size_t)n * 32 + lane] = make_float2(v0 - l, v1 - l);
}

// ======================= launch ==============================
extern "C" void kernel_launch(void* const* d_in, const int* in_sizes, int n_in,
                              void* d_out, int out_size) {
    const float* x   = (const float*)d_in[0];
    const int*   row = (const int*)d_in[1];
    const int*   col = (const int*)d_in[2];
    const float* W1  = (const float*)d_in[3];
    const float* b1  = (const float*)d_in[4];
    const float* lng = (const float*)d_in[5];
    const float* lnb = (const float*)d_in[6];
    const float* W2  = (const float*)d_in[7];
    const float* b2  = (const float*)d_in[8];
    float* out = (float*)d_out;

    void *p_h, *p_acc, *p_dr, *p_hist;
    cudaGetSymbolAddress(&p_h, g_h);
    cudaGetSymbolAddress(&p_acc, g_acc);
    cudaGetSymbolAddress(&p_dr, g_dr);
    cudaGetSymbolAddress(&p_hist, g_hist);
    float* gh = (float*)p_h;
    float* gacc = (float*)p_acc;

    const size_t smem1 = (128 * 128 + 64 * 132) * sizeof(float);   // 99328
    const size_t smem2 = (128 * 64 + 128 * 132) * sizeof(float);   // 100352
    cudaFuncSetAttribute(gemm_kernel<128>, cudaFuncAttributeMaxDynamicSharedMemorySize, (int)smem1);
    cudaFuncSetAttribute(gemm_kernel<64>,  cudaFuncAttributeMaxDynamicSharedMemorySize, (int)smem2);

    const int NB_NODE_T = (Nn + 255) / 256;
    const int NB_NODE_W = (Nn * 32) / 256;     // warp-per-node, 12500 exact
    const int NB_EDGE_T = (Ee + 255) / 256;

    // ---- CSC build ----
    cudaMemsetAsync(p_hist, 0, NSCAN * sizeof(int));
    hist_kernel<<<NB_EDGE_T, 256>>>(col);
    scan1_kernel<<<SCAN_B, 1024>>>();
    scan2_kernel<<<1, 128>>>();
    scan3_kernel<<<SCAN_B, 1024>>>();
    scatter_kernel<<<NB_EDGE_T, 256>>>(row, col);

    // ---- layer 1 ----
    cudaMemsetAsync(p_dr, 0, Nn * sizeof(float));
    rnrm_kernel<<<NB_NODE_W, 256>>>(x);
    gemm_kernel<128><<<(Nn + 63) / 64, 256, smem1>>>(x, W1, gh);
    edge_dot<<<NB_NODE_W, 256>>>(x);
    dinv_kernel<<<NB_NODE_T, 256>>>();
    edge_w_kernel<<<NB_NODE_W, 256>>>();
    fused1_kernel<<<NB_NODE_W, 256>>>(gh, b1, lng, lnb, gacc);

    // ---- layer 2 ----
    cudaMemsetAsync(p_dr, 0, Nn * sizeof(float));
    gemm_kernel<64><<<(Nn + 127) / 128, 256, smem2>>>(gacc, W2, gh);
    edge_dot<<<NB_NODE_W, 256>>>(gacc);
    dinv_kernel<<<NB_NODE_T, 256>>>();
    edge_w_kernel<<<NB_NODE_W, 256>>>();
    fused2_kernel<<<NB_NODE_W, 256>>>(gh, b2, out);
}

// round 4
// speedup vs baseline: 1.5897x; 1.0383x over previous
#include <cuda_runtime.h>
#include <cuda_fp16.h>
#include <math.h>

#define Nn 100000
#define Ee 1600000
#define NSCAN (Nn + 1)
#define SCAN_B 98   // ceil(100001/1024)
#define FIX_MARGIN 2e-3f

// ---------------- scratch (__device__ globals; no runtime allocation) ----------------
__device__ __align__(16) float g_h[(size_t)Nn * 128];   // h1 = x@W1 ; later hW2 (layer2)
__device__ __align__(16) float g_acc[(size_t)Nn * 128]; // relu(LN(...)) output of layer 1
__device__ __align__(16) __half g_xh[(size_t)Nn * 128]; // fp16 copy of features (per layer)
__device__ __align__(16) float g_w[Ee];                 // sims, then edge weights (CSC order)
__device__ int g_srow[Ee];                              // row index per CSC-sorted edge
__device__ int g_fixe[Ee];                              // borderline edge list (CSC pos)
__device__ int g_fixc[Ee];                              // col node of borderline edge
__device__ int g_nfix[2];                               // per-layer counters
__device__ int g_hist[SCAN_B * 1024];
__device__ int g_ptr[SCAN_B * 1024];                    // CSC col pointers (exclusive scan)
__device__ int g_pos[Nn];
__device__ int g_bsum[SCAN_B], g_boff[SCAN_B];
__device__ float g_rnrm[Nn];                            // 1/max(||f||, eps)
__device__ float g_dra[Nn];                             // layer-1 deg_row -> dinv1
__device__ float g_drb[Nn];                             // layer-2 deg_row -> dinv1
__device__ float g_cnt[Nn];                             // selfw = exp(1/(kept_in+1))
__device__ float g_d2[Nn];                              // dinv2 = rsqrt(gcn degree)

__device__ __forceinline__ float warp_sum(float v) {
    #pragma unroll
    for (int o = 16; o; o >>= 1) v += __shfl_xor_sync(0xFFFFFFFFu, v, o);
    return v;
}
__device__ __forceinline__ float warp_max(float v) {
    #pragma unroll
    for (int o = 16; o; o >>= 1) v = fmaxf(v, __shfl_xor_sync(0xFFFFFFFFu, v, o));
    return v;
}

// ======================= CSC build ==================
__global__ void hist_kernel(const int* __restrict__ col) {
    int e = blockIdx.x * blockDim.x + threadIdx.x;
    if (e < Ee) atomicAdd(&g_hist[__ldg(col + e)], 1);
}

__global__ void scan1_kernel() {
    __shared__ int s[1024];
    int tid = threadIdx.x;
    int i = blockIdx.x * 1024 + tid;
    int v = (i < NSCAN) ? g_hist[i] : 0;
    s[tid] = v;
    __syncthreads();
    #pragma unroll
    for (int off = 1; off < 1024; off <<= 1) {
        int t = (tid >= off) ? s[tid - off] : 0;
        __syncthreads();
        s[tid] += t;
        __syncthreads();
    }
    g_ptr[i] = s[tid] - v;
    if (tid == 1023) g_bsum[blockIdx.x] = s[1023];
}

__global__ void scan2_kernel() {
    __shared__ int s[128];
    int tid = threadIdx.x;
    int v = (tid < SCAN_B) ? g_bsum[tid] : 0;
    s[tid] = v;
    __syncthreads();
    #pragma unroll
    for (int off = 1; off < 128; off <<= 1) {
        int t = (tid >= off) ? s[tid - off] : 0;
        __syncthreads();
        s[tid] += t;
        __syncthreads();
    }
    if (tid < SCAN_B) g_boff[tid] = s[tid] - v;
}

__global__ void scan3_kernel() {
    int i = blockIdx.x * 1024 + threadIdx.x;
    int val = g_ptr[i] + g_boff[blockIdx.x];
    g_ptr[i] = val;
    if (i < Nn) g_pos[i] = val;
}

__global__ void scatter_kernel(const int* __restrict__ row, const int* __restrict__ col) {
    int e = blockIdx.x * blockDim.x + threadIdx.x;
    if (e >= Ee) return;
    int c = __ldg(col + e);
    int p = atomicAdd(&g_pos[c], 1);
    g_srow[p] = __ldg(row + e);
}

// ======================= per-layer stages ==============================

// per-node reciprocal norm + fp16 copy (warp per node)
__global__ void rnrm_kernel(const float* __restrict__ F, __half* __restrict__ Fh) {
    int n = (blockIdx.x * blockDim.x + threadIdx.x) >> 5;
    int lane = threadIdx.x & 31;
    if (n >= Nn) return;
    float4 v = ((const float4*)F)[(size_t)n * 32 + lane];
    __half2 h0 = __floats2half2_rn(v.x, v.y);
    __half2 h1 = __floats2half2_rn(v.z, v.w);
    uint2 u;
    u.x = *reinterpret_cast<unsigned int*>(&h0);
    u.y = *reinterpret_cast<unsigned int*>(&h1);
    ((uint2*)Fh)[(size_t)n * 32 + lane] = u;
    float s = warp_sum(v.x * v.x + v.y * v.y + v.z * v.z + v.w * v.w);
    if (lane == 0) g_rnrm[n] = 1.0f / fmaxf(sqrtf(s), 1e-8f);
}

__device__ __forceinline__ float dot8h(const uint4& a, const float* f) {
    float2 t; float s;
    t = __half22float2(*(const __half2*)&a.x); s  = t.x * f[0] + t.y * f[1];
    t = __half22float2(*(const __half2*)&a.y); s += t.x * f[2] + t.y * f[3];
    t = __half22float2(*(const __half2*)&a.z); s += t.x * f[4] + t.y * f[5];
    t = __half22float2(*(const __half2*)&a.w); s += t.x * f[6] + t.y * f[7];
    return s;
}

__device__ __forceinline__ void finalize_edge(int e, int r, float s, float rc, int n,
                                              float* __restrict__ dr, int layer) {
    float sim = s * g_rnrm[r] * rc;
    float d = sim - 0.1f;
    if (fabsf(d) < FIX_MARGIN) {
        int p = atomicAdd(&g_nfix[layer], 1);
        g_fixe[p] = e;
        g_fixc[p] = n;
    } else if (d >= 0.0f) {
        g_w[e] = sim;
        atomicAdd(dr + r, sim);
    } else {
        g_w[e] = 0.0f;
    }
}

// cosine sims from fp16 copies; 16 lanes per edge, 4 edges per iteration.
__global__ void edge_dot_h(const __half* __restrict__ Fh, float* __restrict__ dr, int layer) {
    int n = (blockIdx.x * blockDim.x + threadIdx.x) >> 5;
    int lane = threadIdx.x & 31;
    if (n >= Nn) return;
    int k = lane & 15;
    int hh = lane >> 4;
    uint4 cv = ((const uint4*)Fh)[(size_t)n * 16 + k];
    float fc[8];
    {
        float2 t;
        t = __half22float2(*(const __half2*)&cv.x); fc[0] = t.x; fc[1] = t.y;
        t = __half22float2(*(const __half2*)&cv.y); fc[2] = t.x; fc[3] = t.y;
        t = __half22float2(*(const __half2*)&cv.z); fc[4] = t.x; fc[5] = t.y;
        t = __half22float2(*(const __half2*)&cv.w); fc[6] = t.x; fc[7] = t.y;
    }
    float rc = g_rnrm[n];
    int beg = g_ptr[n], end = g_ptr[n + 1];
    for (int i = beg; i < end; i += 4) {
        int m = end - i;
        bool v0 = hh < m;
        bool v1 = (2 + hh) < m;
        int e0 = i + hh, e1 = i + 2 + hh;
        int r0 = __ldg(g_srow + (v0 ? e0 : i));
        int r1 = __ldg(g_srow + (v1 ? e1 : i));
        uint4 a0 = ((const uint4*)Fh)[(size_t)r0 * 16 + k];
        uint4 a1 = ((const uint4*)Fh)[(size_t)r1 * 16 + k];
        float s0 = dot8h(a0, fc);
        float s1 = dot8h(a1, fc);
        #pragma unroll
        for (int o = 8; o; o >>= 1) {
            s0 += __shfl_xor_sync(0xFFFFFFFFu, s0, o);
            s1 += __shfl_xor_sync(0xFFFFFFFFu, s1, o);
        }
        if (k == 0) {
            if (v0) finalize_edge(e0, r0, s0, rc, n, dr, layer);
            if (v1) finalize_edge(e1, r1, s1, rc, n, dr, layer);
        }
    }
}

// exact fp32 recompute for borderline edges (warp per listed edge)
__global__ void fix_kernel(const float* __restrict__ F, float* __restrict__ dr, int layer) {
    int w = (blockIdx.x * blockDim.x + threadIdx.x) >> 5;
    int lane = threadIdx.x & 31;
    int nw = (gridDim.x * blockDim.x) >> 5;
    int nf = g_nfix[layer];
    for (int idx = w; idx < nf; idx += nw) {
        int e = g_fixe[idx], c = g_fixc[idx];
        int r = __ldg(g_srow + e);
        float4 a = ((const float4*)F)[(size_t)r * 32 + lane];
        float4 b = ((const float4*)F)[(size_t)c * 32 + lane];
        float s = warp_sum(a.x * b.x + a.y * b.y + a.z * b.z + a.w * b.w);
        if (lane == 0) {
            float sim = s * g_rnrm[r] * g_rnrm[c];
            if (sim >= 0.1f) {
                g_w[e] = sim;
                atomicAdd(dr + r, sim);
            } else {
                g_w[e] = 0.0f;
            }
        }
    }
}

// deg_row -> dinv1
__global__ void dinv_kernel(float* __restrict__ dr) {
    int n = blockIdx.x * blockDim.x + threadIdx.x;
    if (n >= Nn) return;
    float d = dr[n];
    dr[n] = (d > 0.0f) ? rsqrtf(d) : 0.0f;
}

// per col-node: edge weights, selfw, gcn degree -> dinv2
__global__ void edge_w_kernel(const float* __restrict__ dr) {
    int n = (blockIdx.x * blockDim.x + threadIdx.x) >> 5;
    int lane = threadIdx.x & 31;
    if (n >= Nn) return;
    int beg = g_ptr[n], end = g_ptr[n + 1];
    float dc = dr[n];
    float deg2 = 0.0f;
    int cnt = 0;
    for (int i = beg + lane; i < end; i += 32) {
        float s = g_w[i];
        if (s > 0.0f) {
            cnt++;
            float w = expf(dr[__ldg(g_srow + i)] * s * dc);
            g_w[i] = w;
            deg2 += w;
        }
    }
    deg2 = warp_sum(deg2);
    cnt = __reduce_add_sync(0xFFFFFFFFu, cnt);
    if (lane == 0) {
        float selfw = expf(1.0f / (float)(cnt + 1));
        g_cnt[n] = selfw;
        g_d2[n] = rsqrtf(deg2 + selfw);
    }
}

// ======================= dense GEMM with packed fma.rn.f32x2 =========================
#define PK2(d, x)  asm("mov.b64 %0, {%1, %1};" : "=l"(d) : "r"(__float_as_uint(x)))
#define FMA2(d, a, b) asm("fma.rn.f32x2 %0, %1, %2, %0;" : "+l"(d) : "l"(a), "l"(b))
#define UPK2(lo, hi, d) asm("mov.b64 {%0, %1}, %2;" : "=r"(lo), "=r"(hi) : "l"(d))

template <int C>
__global__ void gemm_kernel(const float* __restrict__ F, const float* __restrict__ W,
                            float* __restrict__ out) {
    constexpr int CG = C / 8;
    constexpr int NG = 256 / CG;
    constexpr int NPT = 4;
    constexpr int TILE = NG * NPT;
    extern __shared__ float sm[];
    float* Ws = sm;
    float* Fs = sm + 128 * C;
    int tid = threadIdx.x;

    for (int i = tid; i < 128 * C / 4; i += 256)
        ((float4*)Ws)[i] = ((const float4*)W)[i];

    int base = blockIdx.x * TILE;
    for (int i = tid; i < TILE * 32; i += 256) {
        int nd = i >> 5, k4 = i & 31;
        float4 v = make_float4(0.f, 0.f, 0.f, 0.f);
        if (base + nd < Nn) v = ((const float4*)F)[(size_t)(base + nd) * 32 + k4];
        *(float4*)(Fs + nd * 132 + k4 * 4) = v;
    }
    __syncthreads();

    int cg = tid % CG, ng = tid / CG;
    unsigned long long acc[NPT][4];
    #pragma unroll
    for (int i = 0; i < NPT; i++)
        #pragma unroll
        for (int j = 0; j < 4; j++) acc[i][j] = 0ull;

    #pragma unroll 4
    for (int k = 0; k < 128; k++) {
        const unsigned long long* bp = (const unsigned long long*)(Ws + k * C + cg * 8);
        unsigned long long B0 = bp[0], B1 = bp[1], B2 = bp[2], B3 = bp[3];
        #pragma unroll
        for (int i = 0; i < NPT; i++) {
            float a = Fs[(ng * NPT + i) * 132 + k];
            unsigned long long ap; PK2(ap, a);
            FMA2(acc[i][0], ap, B0);
            FMA2(acc[i][1], ap, B1);
            FMA2(acc[i][2], ap, B2);
            FMA2(acc[i][3], ap, B3);
        }
    }

    #pragma unroll
    for (int i = 0; i < NPT; i++) {
        int n = base + ng * NPT + i;
        if (n < Nn) {
            unsigned int o[8];
            #pragma unroll
            for (int j = 0; j < 4; j++) UPK2(o[2 * j], o[2 * j + 1], acc[i][j]);
            *(uint4*)(out + (size_t)n * C + cg * 8) = make_uint4(o[0], o[1], o[2], o[3]);
            *(uint4*)(out + (size_t)n * C + cg * 8 + 4) = make_uint4(o[4], o[5], o[6], o[7]);
        }
    }
}

// ========== fused layer-1 aggregate: gather + self + b1 + LN + ReLU (+ fp16 copy + rnrm) ==========
__global__ void fused1_kernel(const float* __restrict__ H, const float* __restrict__ b1,
                              const float* __restrict__ lng, const float* __restrict__ lnb,
                              float* __restrict__ O, __half* __restrict__ Oh) {
    int n = (blockIdx.x * blockDim.x + threadIdx.x) >> 5;
    int lane = threadIdx.x & 31;
    if (n >= Nn) return;
    int beg = g_ptr[n], end = g_ptr[n + 1];
    float d2n = g_d2[n];
    float sc = g_cnt[n] * d2n;
    float4 hv = ((const float4*)H)[(size_t)n * 32 + lane];
    float4 acc = make_float4(sc * hv.x, sc * hv.y, sc * hv.z, sc * hv.w);
    for (int i = beg; i < end; i += 4) {
        int m = end - i;
        int i1 = i + (m > 1 ? 1 : 0);
        int i2 = i + (m > 2 ? 2 : 0);
        int i3 = i + (m > 3 ? 3 : 0);
        float w0 = g_w[i];
        float w1 = (m > 1) ? g_w[i1] : 0.0f;
        float w2 = (m > 2) ? g_w[i2] : 0.0f;
        float w3 = (m > 3) ? g_w[i3] : 0.0f;
        int r0 = __ldg(g_srow + i);
        int r1 = __ldg(g_srow + i1);
        int r2 = __ldg(g_srow + i2);
        int r3 = __ldg(g_srow + i3);
        if (w0 != 0.0f) {
            float cf = w0 * g_d2[r0];
            float4 h = ((const float4*)H)[(size_t)r0 * 32 + lane];
            acc.x += cf * h.x; acc.y += cf * h.y; acc.z += cf * h.z; acc.w += cf * h.w;
        }
        if (w1 != 0.0f) {
            float cf = w1 * g_d2[r1];
            float4 h = ((const float4*)H)[(size_t)r1 * 32 + lane];
            acc.x += cf * h.x; acc.y += cf * h.y; acc.z += cf * h.z; acc.w += cf * h.w;
        }
        if (w2 != 0.0f) {
            float cf = w2 * g_d2[r2];
            float4 h = ((const float4*)H)[(size_t)r2 * 32 + lane];
            acc.x += cf * h.x; acc.y += cf * h.y; acc.z += cf * h.z; acc.w += cf * h.w;
        }
        if (w3 != 0.0f) {
            float cf = w3 * g_d2[r3];
            float4 h = ((const float4*)H)[(size_t)r3 * 32 + lane];
            acc.x += cf * h.x; acc.y += cf * h.y; acc.z += cf * h.z; acc.w += cf * h.w;
        }
    }
    float4 bv = ((const float4*)b1)[lane];
    float vx = acc.x * d2n + bv.x, vy = acc.y * d2n + bv.y;
    float vz = acc.z * d2n + bv.z, vw = acc.w * d2n + bv.w;
    float mu = warp_sum(vx + vy + vz + vw) * (1.0f / 128.0f);
    float dx = vx - mu, dy = vy - mu, dz = vz - mu, dw = vw - mu;
    float q = warp_sum(dx * dx + dy * dy + dz * dz + dw * dw);
    float rs = rsqrtf(q * (1.0f / 128.0f) + 1e-5f);
    float4 gv = ((const float4*)lng)[lane];
    float4 ob = ((const float4*)lnb)[lane];
    float4 o;
    o.x = fmaxf(dx * rs * gv.x + ob.x, 0.0f);
    o.y = fmaxf(dy * rs * gv.y + ob.y, 0.0f);
    o.z = fmaxf(dz * rs * gv.z + ob.z, 0.0f);
    o.w = fmaxf(dw * rs * gv.w + ob.w, 0.0f);
    ((float4*)O)[(size_t)n * 32 + lane] = o;
    __half2 h0 = __floats2half2_rn(o.x, o.y);
    __half2 h1 = __floats2half2_rn(o.z, o.w);
    uint2 u;
    u.x = *reinterpret_cast<unsigned int*>(&h0);
    u.y = *reinterpret_cast<unsigned int*>(&h1);
    ((uint2*)Oh)[(size_t)n * 32 + lane] = u;
    float ss = warp_sum(o.x * o.x + o.y * o.y + o.z * o.z + o.w * o.w);
    if (lane == 0) g_rnrm[n] = 1.0f / fmaxf(sqrtf(ss), 1e-8f);
}

// ========== fused layer-2 aggregate: gather + self + b2 + log_softmax ==========
__global__ void fused2_kernel(const float* __restrict__ H, const float* __restrict__ b2,
                              float* __restrict__ out) {
    int n = (blockIdx.x * blockDim.x + threadIdx.x) >> 5;
    int lane = threadIdx.x & 31;
    if (n >= Nn) return;
    int beg = g_ptr[n], end = g_ptr[n + 1];
    float d2n = g_d2[n];
    float sc = g_cnt[n] * d2n;
    float2 hv = ((const float2*)H)[(size_t)n * 32 + lane];
    float2 acc = make_float2(sc * hv.x, sc * hv.y);
    for (int i = beg; i < end; i += 4) {
        int m = end - i;
        int i1 = i + (m > 1 ? 1 : 0);
        int i2 = i + (m > 2 ? 2 : 0);
        int i3 = i + (m > 3 ? 3 : 0);
        float w0 = g_w[i];
        float w1 = (m > 1) ? g_w[i1] : 0.0f;
        float w2 = (m > 2) ? g_w[i2] : 0.0f;
        float w3 = (m > 3) ? g_w[i3] : 0.0f;
        int r0 = __ldg(g_srow + i);
        int r1 = __ldg(g_srow + i1);
        int r2 = __ldg(g_srow + i2);
        int r3 = __ldg(g_srow + i3);
        if (w0 != 0.0f) {
            float cf = w0 * g_d2[r0];
            float2 h = ((const float2*)H)[(size_t)r0 * 32 + lane];
            acc.x += cf * h.x; acc.y += cf * h.y;
        }
        if (w1 != 0.0f) {
            float cf = w1 * g_d2[r1];
            float2 h = ((const float2*)H)[(size_t)r1 * 32 + lane];
            acc.x += cf * h.x; acc.y += cf * h.y;
        }
        if (w2 != 0.0f) {
            float cf = w2 * g_d2[r2];
            float2 h = ((const float2*)H)[(size_t)r2 * 32 + lane];
            acc.x += cf * h.x; acc.y += cf * h.y;
        }
        if (w3 != 0.0f) {
            float cf = w3 * g_d2[r3];
            float2 h = ((const float2*)H)[(size_t)r3 * 32 + lane];
            acc.x += cf * h.x; acc.y += cf * h.y;
        }
    }
    float2 bv = ((const float2*)b2)[lane];
    float v0 = acc.x * d2n + bv.x;
    float v1 = acc.y * d2n + bv.y;
    float m = warp_max(fmaxf(v0, v1));
    float s = warp_sum(expf(v0 - m) + expf(v1 - m));
    float l = m + logf(s);
    ((float2*)out)[(size_t)n * 32 + lane] = make_float2(v0 - l, v1 - l);
}

// ======================= launch ==============================
extern "C" void kernel_launch(void* const* d_in, const int* in_sizes, int n_in,
                              void* d_out, int out_size) {
    const float* x   = (const float*)d_in[0];
    const int*   row = (const int*)d_in[1];
    const int*   col = (const int*)d_in[2];
    const float* W1  = (const float*)d_in[3];
    const float* b1  = (const float*)d_in[4];
    const float* lng = (const float*)d_in[5];
    const float* lnb = (const float*)d_in[6];
    const float* W2  = (const float*)d_in[7];
    const float* b2  = (const float*)d_in[8];
    float* out = (float*)d_out;

    void *p_h, *p_acc, *p_xh, *p_dra, *p_drb, *p_hist, *p_nfix;
    cudaGetSymbolAddress(&p_h, g_h);
    cudaGetSymbolAddress(&p_acc, g_acc);
    cudaGetSymbolAddress(&p_xh, g_xh);
    cudaGetSymbolAddress(&p_dra, g_dra);
    cudaGetSymbolAddress(&p_drb, g_drb);
    cudaGetSymbolAddress(&p_hist, g_hist);
    cudaGetSymbolAddress(&p_nfix, g_nfix);
    float* gh = (float*)p_h;
    float* gacc = (float*)p_acc;
    __half* gxh = (__half*)p_xh;
    float* dra = (float*)p_dra;
    float* drb = (float*)p_drb;

    // one-time stream/event setup (host resources; device work stays identical per call)
    static cudaStream_t s1 = nullptr;
    static cudaEvent_t evF1, evG1, evF2, evG2;
    if (s1 == nullptr) {
        cudaStreamCreateWithFlags(&s1, cudaStreamNonBlocking);
        cudaEventCreateWithFlags(&evF1, cudaEventDisableTiming);
        cudaEventCreateWithFlags(&evG1, cudaEventDisableTiming);
        cudaEventCreateWithFlags(&evF2, cudaEventDisableTiming);
        cudaEventCreateWithFlags(&evG2, cudaEventDisableTiming);
    }

    const size_t smem1 = (128 * 128 + 64 * 132) * sizeof(float);
    const size_t smem2 = (128 * 64 + 128 * 132) * sizeof(float);
    cudaFuncSetAttribute(gemm_kernel<128>, cudaFuncAttributeMaxDynamicSharedMemorySize, (int)smem1);
    cudaFuncSetAttribute(gemm_kernel<64>,  cudaFuncAttributeMaxDynamicSharedMemorySize, (int)smem2);

    const int NB_NODE_T = (Nn + 255) / 256;
    const int NB_NODE_W = (Nn * 32) / 256;
    const int NB_EDGE_T = (Ee + 255) / 256;

    // ---- upfront zeroing ----
    cudaMemsetAsync(p_hist, 0, NSCAN * sizeof(int));
    cudaMemsetAsync(p_dra,  0, Nn * sizeof(float));
    cudaMemsetAsync(p_drb,  0, Nn * sizeof(float));
    cudaMemsetAsync(p_nfix, 0, 2 * sizeof(int));

    // ---- fork: GEMM1 on s1, overlapping CSC build + attention chain ----
    cudaEventRecord(evF1, 0);
    cudaStreamWaitEvent(s1, evF1, 0);
    gemm_kernel<128><<<(Nn + 63) / 64, 256, smem1, s1>>>(x, W1, gh);
    cudaEventRecord(evG1, s1);

    // ---- CSC build + layer-1 attention (stream 0) ----
    hist_kernel<<<NB_EDGE_T, 256>>>(col);
    scan1_kernel<<<SCAN_B, 1024>>>();
    scan2_kernel<<<1, 128>>>();
    scan3_kernel<<<SCAN_B, 1024>>>();
    scatter_kernel<<<NB_EDGE_T, 256>>>(row, col);
    rnrm_kernel<<<NB_NODE_W, 256>>>(x, gxh);
    edge_dot_h<<<NB_NODE_W, 256>>>(gxh, dra, 0);
    fix_kernel<<<256, 256>>>(x, dra, 0);
    dinv_kernel<<<NB_NODE_T, 256>>>(dra);
    edge_w_kernel<<<NB_NODE_W, 256>>>(dra);
    cudaStreamWaitEvent(0, evG1, 0);
    fused1_kernel<<<NB_NODE_W, 256>>>(gh, b1, lng, lnb, gacc, gxh);

    // ---- fork: GEMM2 on s1, overlapping layer-2 attention chain ----
    cudaEventRecord(evF2, 0);
    cudaStreamWaitEvent(s1, evF2, 0);
    gemm_kernel<64><<<(Nn + 127) / 128, 256, smem2, s1>>>(gacc, W2, gh);
    cudaEventRecord(evG2, s1);

    // ---- layer-2 attention (stream 0) ----
    edge_dot_h<<<NB_NODE_W, 256>>>(gxh, drb, 1);
    fix_kernel<<<256, 256>>>(gacc, drb, 1);
    dinv_kernel<<<NB_NODE_T, 256>>>(drb);
    edge_w_kernel<<<NB_NODE_W, 256>>>(drb);
    cudaStreamWaitEvent(0, evG2, 0);
    fused2_kernel<<<NB_NODE_W, 256>>>(gh, b2, out);
}